// round 6
// baseline (speedup 1.0000x reference)
#include <cuda_runtime.h>
#include <cuda_bf16.h>
#include <math.h>
#include <stdint.h>

// ---------------- problem constants ----------------
#define N_NODES   32000
#define NUM_G     32
#define NPG       1000
#define N_EDGES   256000
#define IN_DIM    1024
#define HID       256
#define NC        8

// ---------------- scratch (device globals; no allocation) ----------------
__device__ int   g_cnt[N_NODES];
__device__ int   g_off[N_NODES + 1];
__device__ int   g_cur[N_NODES];
__device__ int   g_csr_src[N_EDGES];
__device__ int   g_csr_dst[N_EDGES];
__device__ float g_Y[(size_t)N_NODES * 512];          // [N,512]: 0-255 = x@Wl1, 256-511 = x@Wr1
__device__ float g_S16[(size_t)N_NODES * 16];         // [N,16]: 0-7 = x@Wla, 8-15 = x@Wra
__device__ float g_Z[(size_t)N_NODES * HID];
__device__ float g_Ss[(size_t)N_NODES * NC];
__device__ float g_Xp[NUM_G * NC * HID];
__device__ float g_Ap[NUM_G * NC * NC];
__device__ float g_Zp[NUM_G * NC * HID];

// ---------------- CSR build ----------------
__global__ void k_zero_cnt() {
    int i = blockIdx.x * blockDim.x + threadIdx.x;
    if (i < N_NODES) g_cnt[i] = 0;
}

__global__ void k_hist(const int* __restrict__ dst) {
    int e = blockIdx.x * blockDim.x + threadIdx.x;
    if (e < N_EDGES) atomicAdd(&g_cnt[dst[e]], 1);
}

// single-pass scan: 1024 threads, thread t owns counts [32t, 32t+32)
__global__ __launch_bounds__(1024) void k_scan() {
    __shared__ int wsum[32];
    int t = threadIdx.x;
    int lane = t & 31, warp = t >> 5;
    int base = t * 32;
    int vals[32];
    int s = 0;
    if (base < N_NODES) {
        #pragma unroll
        for (int i = 0; i < 32; i++) { vals[i] = g_cnt[base + i]; s += vals[i]; }
    }
    int v = s;
    #pragma unroll
    for (int o = 1; o < 32; o <<= 1) {
        int u = __shfl_up_sync(0xFFFFFFFFu, v, o);
        if (lane >= o) v += u;
    }
    if (lane == 31) wsum[warp] = v;
    __syncthreads();
    if (warp == 0) {
        int w = wsum[lane];
        #pragma unroll
        for (int o = 1; o < 32; o <<= 1) {
            int u = __shfl_up_sync(0xFFFFFFFFu, w, o);
            if (lane >= o) w += u;
        }
        wsum[lane] = w;
    }
    __syncthreads();
    int excl = v - s + (warp > 0 ? wsum[warp - 1] : 0);
    if (base < N_NODES) {
        int run = excl;
        #pragma unroll
        for (int i = 0; i < 32; i++) {
            g_off[base + i] = run;
            g_cur[base + i] = run;
            run += vals[i];
        }
    }
    if (t == 1023) g_off[N_NODES] = wsum[31];
}

__global__ void k_scatter(const int* __restrict__ src, const int* __restrict__ dst) {
    int e = blockIdx.x * blockDim.x + threadIdx.x;
    if (e < N_EDGES) {
        int d = dst[e];
        int p = atomicAdd(&g_cur[d], 1);
        g_csr_src[p] = src[e];
        g_csr_dst[p] = d;
    }
}

// ---------------- tf32 helpers ----------------
__device__ __forceinline__ uint32_t f2tf32(float f) {
    uint32_t r;
    asm("cvt.rna.tf32.f32 %0, %1;" : "=r"(r) : "f"(f));
    return r;
}
// split v into tf32 hi + tf32 lo, stored as float bit patterns
__device__ __forceinline__ void split_store(float v, float* hp, float* lp) {
    uint32_t h = f2tf32(v);
    float hf = __uint_as_float(h);
    *hp = hf;
    *lp = __uint_as_float(f2tf32(v - hf));
}

#define MMA_TF32(d, a0, a1, a2, a3, b0, b1)                                        \
    asm volatile("mma.sync.aligned.m16n8k8.row.col.f32.tf32.tf32.f32 "             \
                 "{%0,%1,%2,%3},{%4,%5,%6,%7},{%8,%9},{%0,%1,%2,%3};"              \
                 : "+f"(d[0]), "+f"(d[1]), "+f"(d[2]), "+f"(d[3])                  \
                 : "r"(a0), "r"(a1), "r"(a2), "r"(a3), "r"(b0), "r"(b1))

// ---------------- Y-GEMM (3xTF32, hi/lo pre-split in smem) ----------------
// Y[:,0:256] = x@Wl1 ; Y[:,256:512] = x@Wr1
// BM=128, BN=64, BK=16; 256 threads (8 warps, 4x2); warp tile 32x32 (2x4 m16n8k8)
// Grid: (8 col-tiles [fast axis -> L2 reuse of x slabs], 250 M-slabs)
#define TY_BM 128
#define TY_BN 64
#define TY_BK 16
#define TY_AS 20   // A smem row stride (floats): conflict-free fragment loads
#define TY_BS 72   // B smem row stride (floats): conflict-free fragment loads

#define A_BUF (TY_BM * TY_AS)          // 2560 floats per buffer
#define B_BUF (TY_BK * TY_BS)          // 1152 floats per buffer
// dynamic smem: Ah[2], Al[2], Bh[2], Bl[2]
#define GY_SMEM_FLOATS (4 * A_BUF + 4 * B_BUF)
#define GY_SMEM_BYTES  (GY_SMEM_FLOATS * 4)

__global__ __launch_bounds__(256) void k_gemmY(const float* __restrict__ x,
                                               const float* __restrict__ Wl,
                                               const float* __restrict__ Wr) {
    extern __shared__ float sdyn[];
    float* sAh = sdyn;                    // [2][TY_BM][TY_AS]
    float* sAl = sAh + 2 * A_BUF;
    float* sBh = sAl + 2 * A_BUF;         // [2][TY_BK][TY_BS]
    float* sBl = sBh + 2 * B_BUF;

    int tid = threadIdx.x;
    int wid = tid >> 5;
    int lane = tid & 31;
    int warp_m = wid >> 1;        // 0..3 : 32-row band
    int warp_n = wid & 1;         // 0..1 : 32-col band
    int lk = lane & 3;
    int lr = lane >> 2;

    int bm = blockIdx.y * TY_BM;              // M-slab (slow axis)
    int col0 = blockIdx.x * TY_BN;            // column tile (fast axis)
    const float* Bsrc = (col0 < 256) ? (Wl + col0) : (Wr + (col0 - 256));

    float acc[2][4][4];
    #pragma unroll
    for (int i = 0; i < 2; i++)
        #pragma unroll
        for (int j = 0; j < 4; j++)
            #pragma unroll
            for (int k = 0; k < 4; k++) acc[i][j][k] = 0.f;

    // A G->S mapping: 512 float4 per tile, 2 per thread
    int a_row0 = tid >> 2;            // 0..63
    int a_f4c  = tid & 3;             // 0..3
    const float* aPtr0 = x + (size_t)(bm + a_row0) * IN_DIM + a_f4c * 4;
    const float* aPtr1 = x + (size_t)(bm + a_row0 + 64) * IN_DIM + a_f4c * 4;
    // B G->S mapping: 256 float4 per tile, 1 per thread
    int b_krow = tid >> 4;            // 0..15
    int b_f4c  = tid & 15;            // 0..15
    const float* bPtr = Bsrc + (size_t)b_krow * HID + b_f4c * 4;

    // store helper offsets
    int aOff0 = a_row0 * TY_AS + a_f4c * 4;
    int aOff1 = (a_row0 + 64) * TY_AS + a_f4c * 4;
    int bOff  = b_krow * TY_BS + b_f4c * 4;

    // prologue: tile kt=0 -> buf 0 (split at store)
    {
        float4 va0 = *(const float4*)(aPtr0);
        float4 va1 = *(const float4*)(aPtr1);
        float4 vb  = *(const float4*)(bPtr);
        split_store(va0.x, sAh + aOff0 + 0, sAl + aOff0 + 0);
        split_store(va0.y, sAh + aOff0 + 1, sAl + aOff0 + 1);
        split_store(va0.z, sAh + aOff0 + 2, sAl + aOff0 + 2);
        split_store(va0.w, sAh + aOff0 + 3, sAl + aOff0 + 3);
        split_store(va1.x, sAh + aOff1 + 0, sAl + aOff1 + 0);
        split_store(va1.y, sAh + aOff1 + 1, sAl + aOff1 + 1);
        split_store(va1.z, sAh + aOff1 + 2, sAl + aOff1 + 2);
        split_store(va1.w, sAh + aOff1 + 3, sAl + aOff1 + 3);
        split_store(vb.x, sBh + bOff + 0, sBl + bOff + 0);
        split_store(vb.y, sBh + bOff + 1, sBl + bOff + 1);
        split_store(vb.z, sBh + bOff + 2, sBl + bOff + 2);
        split_store(vb.w, sBh + bOff + 3, sBl + bOff + 3);
    }
    __syncthreads();

    int buf = 0;
    for (int kt = 0; kt < IN_DIM; kt += TY_BK) {
        int ktn = kt + TY_BK;
        float4 va0, va1, vb;
        if (ktn < IN_DIM) {
            va0 = *(const float4*)(aPtr0 + ktn);
            va1 = *(const float4*)(aPtr1 + ktn);
            vb  = *(const float4*)(bPtr + (size_t)ktn * HID);
        }

        const float* Ah = sAh + buf * A_BUF;
        const float* Al = sAl + buf * A_BUF;
        const float* Bh = sBh + buf * B_BUF;
        const float* Bl = sBl + buf * B_BUF;

        #pragma unroll
        for (int ks = 0; ks < 2; ks++) {
            // A fragments (2 m-tiles), hi and lo direct from smem
            uint32_t ah[2][4], al[2][4];
            #pragma unroll
            for (int tm = 0; tm < 2; tm++) {
                int r = warp_m * 32 + tm * 16 + lr;
                int c = ks * 8 + lk;
                ah[tm][0] = __float_as_uint(Ah[r * TY_AS + c]);
                ah[tm][1] = __float_as_uint(Ah[(r + 8) * TY_AS + c]);
                ah[tm][2] = __float_as_uint(Ah[r * TY_AS + c + 4]);
                ah[tm][3] = __float_as_uint(Ah[(r + 8) * TY_AS + c + 4]);
                al[tm][0] = __float_as_uint(Al[r * TY_AS + c]);
                al[tm][1] = __float_as_uint(Al[(r + 8) * TY_AS + c]);
                al[tm][2] = __float_as_uint(Al[r * TY_AS + c + 4]);
                al[tm][3] = __float_as_uint(Al[(r + 8) * TY_AS + c + 4]);
            }
            // B fragments (4 n-tiles)
            uint32_t bh[4][2], bl[4][2];
            #pragma unroll
            for (int tn = 0; tn < 4; tn++) {
                int c = warp_n * 32 + tn * 8 + lr;
                int kr = ks * 8 + lk;
                bh[tn][0] = __float_as_uint(Bh[kr * TY_BS + c]);
                bh[tn][1] = __float_as_uint(Bh[(kr + 4) * TY_BS + c]);
                bl[tn][0] = __float_as_uint(Bl[kr * TY_BS + c]);
                bl[tn][1] = __float_as_uint(Bl[(kr + 4) * TY_BS + c]);
            }
            // 3xTF32: C += Ah*Bh + Ah*Bl + Al*Bh
            #pragma unroll
            for (int tm = 0; tm < 2; tm++)
                #pragma unroll
                for (int tn = 0; tn < 4; tn++) {
                    MMA_TF32(acc[tm][tn], ah[tm][0], ah[tm][1], ah[tm][2], ah[tm][3],
                             bh[tn][0], bh[tn][1]);
                    MMA_TF32(acc[tm][tn], ah[tm][0], ah[tm][1], ah[tm][2], ah[tm][3],
                             bl[tn][0], bl[tn][1]);
                    MMA_TF32(acc[tm][tn], al[tm][0], al[tm][1], al[tm][2], al[tm][3],
                             bh[tn][0], bh[tn][1]);
                }
        }

        if (ktn < IN_DIM) {
            int nb = buf ^ 1;
            float* nAh = sAh + nb * A_BUF;
            float* nAl = sAl + nb * A_BUF;
            float* nBh = sBh + nb * B_BUF;
            float* nBl = sBl + nb * B_BUF;
            split_store(va0.x, nAh + aOff0 + 0, nAl + aOff0 + 0);
            split_store(va0.y, nAh + aOff0 + 1, nAl + aOff0 + 1);
            split_store(va0.z, nAh + aOff0 + 2, nAl + aOff0 + 2);
            split_store(va0.w, nAh + aOff0 + 3, nAl + aOff0 + 3);
            split_store(va1.x, nAh + aOff1 + 0, nAl + aOff1 + 0);
            split_store(va1.y, nAh + aOff1 + 1, nAl + aOff1 + 1);
            split_store(va1.z, nAh + aOff1 + 2, nAl + aOff1 + 2);
            split_store(va1.w, nAh + aOff1 + 3, nAl + aOff1 + 3);
            split_store(vb.x, nBh + bOff + 0, nBl + bOff + 0);
            split_store(vb.y, nBh + bOff + 1, nBl + bOff + 1);
            split_store(vb.z, nBh + bOff + 2, nBl + bOff + 2);
            split_store(vb.w, nBh + bOff + 3, nBl + bOff + 3);
            __syncthreads();
            buf = nb;
        }
    }

    // epilogue: C fragment -> g_Y
    #pragma unroll
    for (int tm = 0; tm < 2; tm++) {
        int row_base = bm + warp_m * 32 + tm * 16 + lr;
        #pragma unroll
        for (int tn = 0; tn < 4; tn++) {
            int col = col0 + warp_n * 32 + tn * 8 + lk * 2;
            float* d0 = g_Y + (size_t)row_base * 512 + col;
            float* d1 = g_Y + (size_t)(row_base + 8) * 512 + col;
            *(float2*)d0 = make_float2(acc[tm][tn][0], acc[tm][tn][1]);
            *(float2*)d1 = make_float2(acc[tm][tn][2], acc[tm][tn][3]);
        }
    }
}

// ---------------- S16 = x @ [Wla | Wra]  [N,16] ----------------
// one warp per node
__global__ __launch_bounds__(256) void k_s16(const float* __restrict__ x,
                                             const float* __restrict__ Wla,
                                             const float* __restrict__ Wra) {
    int node = (blockIdx.x * blockDim.x + threadIdx.x) >> 5;
    int lane = threadIdx.x & 31;
    if (node >= N_NODES) return;
    const float4* Wl4 = (const float4*)Wla;
    const float4* Wr4 = (const float4*)Wra;
    float al[8], ar[8];
    #pragma unroll
    for (int c = 0; c < 8; c++) { al[c] = 0.f; ar[c] = 0.f; }
    const float* xr = x + (size_t)node * IN_DIM;
    for (int k0 = 0; k0 < IN_DIM; k0 += 32) {
        int k = k0 + lane;
        float xx = xr[k];
        float4 l0 = Wl4[k * 2], l1 = Wl4[k * 2 + 1];
        float4 r0 = Wr4[k * 2], r1 = Wr4[k * 2 + 1];
        al[0] += xx * l0.x; al[1] += xx * l0.y; al[2] += xx * l0.z; al[3] += xx * l0.w;
        al[4] += xx * l1.x; al[5] += xx * l1.y; al[6] += xx * l1.z; al[7] += xx * l1.w;
        ar[0] += xx * r0.x; ar[1] += xx * r0.y; ar[2] += xx * r0.z; ar[3] += xx * r0.w;
        ar[4] += xx * r1.x; ar[5] += xx * r1.y; ar[6] += xx * r1.z; ar[7] += xx * r1.w;
    }
    #pragma unroll
    for (int o = 16; o > 0; o >>= 1) {
        #pragma unroll
        for (int c = 0; c < 8; c++) {
            al[c] += __shfl_xor_sync(0xFFFFFFFFu, al[c], o);
            ar[c] += __shfl_xor_sync(0xFFFFFFFFu, ar[c], o);
        }
    }
    if (lane == 0) {
        float4* out = (float4*)(g_S16 + (size_t)node * 16);
        out[0] = make_float4(al[0], al[1], al[2], al[3]);
        out[1] = make_float4(al[4], al[5], al[6], al[7]);
        out[2] = make_float4(ar[0], ar[1], ar[2], ar[3]);
        out[3] = make_float4(ar[4], ar[5], ar[6], ar[7]);
    }
}

// ---------------- fused aggregation + Z + softmax(S) ----------------
// one warp per node; lane owns 8 cols of the 256 Yl/Yr cols
__global__ __launch_bounds__(256) void k_agg_fuse(const float* __restrict__ bl1,
                                                  const float* __restrict__ bla) {
    int node = (blockIdx.x * blockDim.x + threadIdx.x) >> 5;
    int lane = threadIdx.x & 31;
    if (node >= N_NODES) return;
    int beg = g_off[node], end = g_off[node + 1];

    float4 a0 = make_float4(0.f, 0.f, 0.f, 0.f);
    float4 a1 = a0;
    float sacc = 0.f;
    for (int p = beg; p < end; p++) {
        int s = g_csr_src[p];
        const float4* row = (const float4*)(g_Y + (size_t)s * 512);
        float4 v0 = row[lane * 2];
        float4 v1 = row[lane * 2 + 1];
        a0.x += v0.x; a0.y += v0.y; a0.z += v0.z; a0.w += v0.w;
        a1.x += v1.x; a1.y += v1.y; a1.z += v1.z; a1.w += v1.w;
        if (lane < 8) sacc += g_S16[(size_t)s * 16 + lane];
    }
    float inv = (end > beg) ? 1.f / (float)(end - beg) : 0.f;

    // Z = relu(aggYl + Yr + bl1)
    const float4* yr = (const float4*)(g_Y + (size_t)node * 512 + 256);
    float4 r0 = yr[lane * 2], r1 = yr[lane * 2 + 1];
    const float4* bb4 = (const float4*)bl1;
    float4 b0 = bb4[lane * 2], b1 = bb4[lane * 2 + 1];
    float4 z0, z1;
    z0.x = fmaxf(a0.x * inv + r0.x + b0.x, 0.f);
    z0.y = fmaxf(a0.y * inv + r0.y + b0.y, 0.f);
    z0.z = fmaxf(a0.z * inv + r0.z + b0.z, 0.f);
    z0.w = fmaxf(a0.w * inv + r0.w + b0.w, 0.f);
    z1.x = fmaxf(a1.x * inv + r1.x + b1.x, 0.f);
    z1.y = fmaxf(a1.y * inv + r1.y + b1.y, 0.f);
    z1.z = fmaxf(a1.z * inv + r1.z + b1.z, 0.f);
    z1.w = fmaxf(a1.w * inv + r1.w + b1.w, 0.f);
    float4* zo = (float4*)(g_Z + (size_t)node * HID);
    zo[lane * 2] = z0;
    zo[lane * 2 + 1] = z1;

    // S = aggSl + Sr + bla ; row softmax over 8 cluster logits (lanes 0..7)
    float sval = 0.f;
    if (lane < 8)
        sval = sacc * inv + g_S16[(size_t)node * 16 + 8 + lane] + bla[lane];
    float m = sval;
    #pragma unroll
    for (int o = 4; o > 0; o >>= 1)
        m = fmaxf(m, __shfl_xor_sync(0xFFFFFFFFu, m, o, 8));
    float e = expf(sval - m);
    float ssum = e;
    #pragma unroll
    for (int o = 4; o > 0; o >>= 1)
        ssum += __shfl_xor_sync(0xFFFFFFFFu, ssum, o, 8);
    if (lane < 8)
        g_Ss[(size_t)node * 8 + lane] = e / ssum;
}

// ---------------- Xp[g,c,h] = sum_i Ss[i,c] * Z[i,h] ----------------
__global__ __launch_bounds__(256) void k_xp() {
    int g = blockIdx.x;
    int t = threadIdx.x;  // h
    __shared__ __align__(16) float sS[64][8];
    float acc[8];
    #pragma unroll
    for (int c = 0; c < 8; c++) acc[c] = 0.f;
    for (int base = 0; base < NPG; base += 64) {
        int nchunk = min(64, NPG - base);
        for (int idx = t; idx < nchunk * 8; idx += 256)
            sS[idx >> 3][idx & 7] = g_Ss[(size_t)(g * NPG + base) * 8 + idx];
        __syncthreads();
        for (int i = 0; i < nchunk; i++) {
            float z = g_Z[(size_t)(g * NPG + base + i) * HID + t];
            #pragma unroll
            for (int c = 0; c < 8; c++) acc[c] += sS[i][c] * z;
        }
        __syncthreads();
    }
    #pragma unroll
    for (int c = 0; c < 8; c++)
        g_Xp[g * (NC * HID) + c * HID + t] = acc[c];
}

// ---------------- Ap[g,i,j] = sum_{edges in g} Ss[src,i]*Ss[dst,j] ----------------
__global__ __launch_bounds__(256) void k_ap() {
    int g = blockIdx.x;
    int tid = threadIdx.x;
    __shared__ __align__(16) float es[256][8];
    __shared__ __align__(16) float ed[256][8];
    __shared__ float apsh[64];
    if (tid < 64) apsh[tid] = 0.f;
    int p0 = g_off[g * NPG];
    int p1 = g_off[(g + 1) * NPG];
    int ij = tid & 63, egrp = tid >> 6;  // 4 edge groups
    int i = ij >> 3, j = ij & 7;
    float acc = 0.f;
    __syncthreads();
    for (int base = p0; base < p1; base += 256) {
        int n = min(256, p1 - base);
        for (int idx = tid; idx < n; idx += 256) {
            int s = g_csr_src[base + idx];
            int d = g_csr_dst[base + idx];
            const float4* Ps = (const float4*)(g_Ss + (size_t)s * 8);
            const float4* Pd = (const float4*)(g_Ss + (size_t)d * 8);
            ((float4*)es[idx])[0] = Ps[0];
            ((float4*)es[idx])[1] = Ps[1];
            ((float4*)ed[idx])[0] = Pd[0];
            ((float4*)ed[idx])[1] = Pd[1];
        }
        __syncthreads();
        for (int e = egrp; e < n; e += 4)
            acc += es[e][i] * ed[e][j];
        __syncthreads();
    }
    atomicAdd(&apsh[ij], acc);
    __syncthreads();
    if (tid < 64) g_Ap[g * 64 + tid] = apsh[tid];
}

// ---------------- pooled SAGE: Zp = relu(agg2@Wl2 + bl2 + Xp@Wr2) ----------------
__global__ __launch_bounds__(256) void k_pool(const float* __restrict__ Wl2,
                                              const float* __restrict__ bl2,
                                              const float* __restrict__ Wr2) {
    int g = blockIdx.x;
    int t = threadIdx.x;  // h
    __shared__ float sXp[8][HID];
    __shared__ float sA2[8][HID];
    __shared__ float smask[8][8];
    __shared__ float sdeg[8];
    #pragma unroll
    for (int c = 0; c < 8; c++) sXp[c][t] = g_Xp[g * (NC * HID) + c * HID + t];
    if (t < 64) smask[t >> 3][t & 7] = (g_Ap[g * 64 + t] != 0.f) ? 1.f : 0.f;
    __syncthreads();
    if (t < 8) {
        float d = 0.f;
        #pragma unroll
        for (int ii = 0; ii < 8; ii++) d += smask[ii][t];
        sdeg[t] = d;
    }
    __syncthreads();
    #pragma unroll
    for (int j = 0; j < 8; j++) {
        float a = 0.f;
        #pragma unroll
        for (int ii = 0; ii < 8; ii++) a += smask[ii][j] * sXp[ii][t];
        float d = sdeg[j];
        sA2[j][t] = (d > 0.f) ? a / d : 0.f;
    }
    __syncthreads();
    float bb = bl2[t];
    #pragma unroll
    for (int j = 0; j < 8; j++) {
        float a = bb;
        for (int k = 0; k < HID; k++)
            a += sA2[j][k] * Wl2[k * HID + t] + sXp[j][k] * Wr2[k * HID + t];
        g_Zp[g * (NC * HID) + j * HID + t] = a > 0.f ? a : 0.f;
    }
}

// ---------------- classifier: out[g] = relu(Zp_flat@Wc1+bc1)@Wc2 + bc2 ----------------
__global__ __launch_bounds__(256) void k_cls(const float* __restrict__ Wc1,
                                             const float* __restrict__ bc1,
                                             const float* __restrict__ Wc2,
                                             const float* __restrict__ bc2,
                                             float* __restrict__ out) {
    int g = blockIdx.x;
    int t = threadIdx.x;  // output unit o
    __shared__ float sZ[NC * HID];
    __shared__ float sh[256];
    #pragma unroll
    for (int u = 0; u < 8; u++) sZ[u * 256 + t] = g_Zp[g * (NC * HID) + u * 256 + t];
    __syncthreads();
    float a = bc1[t];
    for (int k = 0; k < NC * HID; k++)
        a += sZ[k] * Wc1[(size_t)k * HID + t];
    float h = a > 0.f ? a : 0.f;
    sh[t] = h * Wc2[t];
    __syncthreads();
    #pragma unroll
    for (int s = 128; s > 0; s >>= 1) {
        if (t < s) sh[t] += sh[t + s];
        __syncthreads();
    }
    if (t == 0) out[g] = sh[0] + bc2[0];
}

// ---------------- launch ----------------
extern "C" void kernel_launch(void* const* d_in, const int* in_sizes, int n_in,
                              void* d_out, int out_size) {
    const float* x   = (const float*)d_in[0];
    const int*   ei  = (const int*)d_in[1];
    // d_in[2] = batch (unused; graph id derived from node index)
    const float* Wl1 = (const float*)d_in[3];
    const float* bl1 = (const float*)d_in[4];
    const float* Wr1 = (const float*)d_in[5];
    const float* Wla = (const float*)d_in[6];
    const float* bla = (const float*)d_in[7];
    const float* Wra = (const float*)d_in[8];
    const float* Wl2 = (const float*)d_in[9];
    const float* bl2 = (const float*)d_in[10];
    const float* Wr2 = (const float*)d_in[11];
    const float* Wc1 = (const float*)d_in[12];
    const float* bc1 = (const float*)d_in[13];
    const float* Wc2 = (const float*)d_in[14];
    const float* bc2 = (const float*)d_in[15];
    float* out = (float*)d_out;

    const int* src = ei;
    const int* dst = ei + N_EDGES;

    // idempotent, host-side, no allocation
    cudaFuncSetAttribute(k_gemmY, cudaFuncAttributeMaxDynamicSharedMemorySize, GY_SMEM_BYTES);

    k_zero_cnt<<<(N_NODES + 255) / 256, 256>>>();
    k_hist<<<(N_EDGES + 255) / 256, 256>>>(dst);
    k_scan<<<1, 1024>>>();
    k_scatter<<<(N_EDGES + 255) / 256, 256>>>(src, dst);
    // col-tile on blockIdx.x (fast axis): consecutive blocks share the same x slab in L2
    k_gemmY<<<dim3(512 / TY_BN, N_NODES / TY_BM), 256, GY_SMEM_BYTES>>>(x, Wl1, Wr1);
    k_s16<<<(N_NODES * 32 + 255) / 256, 256>>>(x, Wla, Wra);
    k_agg_fuse<<<(N_NODES * 32 + 255) / 256, 256>>>(bl1, bla);
    k_xp<<<NUM_G, 256>>>();
    k_ap<<<NUM_G, 256>>>();
    k_pool<<<NUM_G, 256>>>(Wl2, bl2, Wr2);
    k_cls<<<NUM_G, 256>>>(Wc1, bc1, Wc2, bc2, out);
}

// round 10
// speedup vs baseline: 1.0034x; 1.0034x over previous
#include <cuda_runtime.h>
#include <cuda_bf16.h>
#include <math.h>
#include <stdint.h>

// ---------------- problem constants ----------------
#define N_NODES   32000
#define NUM_G     32
#define NPG       1000
#define N_EDGES   256000
#define IN_DIM    1024
#define HID       256
#define NC        8

// ---------------- scratch (device globals; no allocation) ----------------
__device__ int   g_cnt[N_NODES];
__device__ int   g_off[N_NODES + 1];
__device__ int   g_cur[N_NODES];
__device__ int   g_csr_src[N_EDGES];
__device__ int   g_csr_dst[N_EDGES];
__device__ float g_Y[(size_t)N_NODES * 512];          // [N,512]: 0-255 = x@Wl1, 256-511 = x@Wr1
__device__ float g_S16[(size_t)N_NODES * 16];
__device__ float g_Z[(size_t)N_NODES * HID];
__device__ float g_Ss[(size_t)N_NODES * NC];
__device__ float g_Xp[NUM_G * NC * HID];
__device__ float g_Ap[NUM_G * NC * NC];
__device__ float g_Zp[NUM_G * NC * HID];
// bf16 hi/lo splits (16B-aligned: accessed through uint2/uint4)
__device__ __align__(16) __nv_bfloat16 g_x_hi[(size_t)N_NODES * IN_DIM];
__device__ __align__(16) __nv_bfloat16 g_x_lo[(size_t)N_NODES * IN_DIM];
__device__ __align__(16) __nv_bfloat16 g_Wb_hi[512 * IN_DIM];   // [n(512)][k(1024)]
__device__ __align__(16) __nv_bfloat16 g_Wb_lo[512 * IN_DIM];

// ---------------- CSR build ----------------
__global__ void k_zero_cnt() {
    int i = blockIdx.x * blockDim.x + threadIdx.x;
    if (i < N_NODES) g_cnt[i] = 0;
}

__global__ void k_hist(const int* __restrict__ dst) {
    int e = blockIdx.x * blockDim.x + threadIdx.x;
    if (e < N_EDGES) atomicAdd(&g_cnt[dst[e]], 1);
}

__global__ __launch_bounds__(1024) void k_scan() {
    __shared__ int wsum[32];
    int t = threadIdx.x;
    int lane = t & 31, warp = t >> 5;
    int base = t * 32;
    int vals[32];
    int s = 0;
    if (base < N_NODES) {
        #pragma unroll
        for (int i = 0; i < 32; i++) { vals[i] = g_cnt[base + i]; s += vals[i]; }
    }
    int v = s;
    #pragma unroll
    for (int o = 1; o < 32; o <<= 1) {
        int u = __shfl_up_sync(0xFFFFFFFFu, v, o);
        if (lane >= o) v += u;
    }
    if (lane == 31) wsum[warp] = v;
    __syncthreads();
    if (warp == 0) {
        int w = wsum[lane];
        #pragma unroll
        for (int o = 1; o < 32; o <<= 1) {
            int u = __shfl_up_sync(0xFFFFFFFFu, w, o);
            if (lane >= o) w += u;
        }
        wsum[lane] = w;
    }
    __syncthreads();
    int excl = v - s + (warp > 0 ? wsum[warp - 1] : 0);
    if (base < N_NODES) {
        int run = excl;
        #pragma unroll
        for (int i = 0; i < 32; i++) {
            g_off[base + i] = run;
            g_cur[base + i] = run;
            run += vals[i];
        }
    }
    if (t == 1023) g_off[N_NODES] = wsum[31];
}

__global__ void k_scatter(const int* __restrict__ src, const int* __restrict__ dst) {
    int e = blockIdx.x * blockDim.x + threadIdx.x;
    if (e < N_EDGES) {
        int d = dst[e];
        int p = atomicAdd(&g_cur[d], 1);
        g_csr_src[p] = src[e];
        g_csr_dst[p] = d;
    }
}

// ---------------- bf16 split conversions ----------------
__device__ __forceinline__ uint32_t pack_bf16(float a, float b) {
    __nv_bfloat162 h = __floats2bfloat162_rn(a, b);
    return *(uint32_t*)&h;
}

// x [32000,1024] fp32 -> g_x_hi/lo bf16
__global__ __launch_bounds__(256) void k_convX(const float* __restrict__ x) {
    size_t f4 = ((size_t)blockIdx.x * 256 + threadIdx.x) * 4;
    const float4* xin = (const float4*)x;
    #pragma unroll
    for (int i = 0; i < 4; i++) {
        float4 v = xin[f4 + i];
        float hx = __bfloat162float(__float2bfloat16_rn(v.x));
        float hy = __bfloat162float(__float2bfloat16_rn(v.y));
        float hz = __bfloat162float(__float2bfloat16_rn(v.z));
        float hw = __bfloat162float(__float2bfloat16_rn(v.w));
        uint2 hi = make_uint2(pack_bf16(hx, hy), pack_bf16(hz, hw));
        uint2 lo = make_uint2(pack_bf16(v.x - hx, v.y - hy), pack_bf16(v.z - hz, v.w - hw));
        ((uint2*)g_x_hi)[f4 + i] = hi;
        ((uint2*)g_x_lo)[f4 + i] = lo;
    }
}

// W -> transposed [n=512][k=1024] bf16 hi/lo
__global__ void k_convW(const float* __restrict__ Wl, const float* __restrict__ Wr) {
    int n = blockIdx.y;
    int k = blockIdx.x * 256 + threadIdx.x;
    float v = (n < 256) ? Wl[(size_t)k * 256 + n] : Wr[(size_t)k * 256 + (n - 256)];
    __nv_bfloat16 h = __float2bfloat16_rn(v);
    g_Wb_hi[n * IN_DIM + k] = h;
    g_Wb_lo[n * IN_DIM + k] = __float2bfloat16_rn(v - __bfloat162float(h));
}

// ---------------- bf16 m16n8k16 MMA ----------------
#define MMA_BF16(d, a, b)                                                          \
    asm volatile("mma.sync.aligned.m16n8k16.row.col.f32.bf16.bf16.f32 "            \
                 "{%0,%1,%2,%3},{%4,%5,%6,%7},{%8,%9},{%0,%1,%2,%3};"              \
                 : "+f"((d)[0]), "+f"((d)[1]), "+f"((d)[2]), "+f"((d)[3])          \
                 : "r"((a)[0]), "r"((a)[1]), "r"((a)[2]), "r"((a)[3]),             \
                   "r"((b)[0]), "r"((b)[1]))

// ---------------- Y-GEMM (3x bf16 split, m16n8k16) ----------------
// Y[:,0:512] = x @ [Wl1|Wr1]; grid (8 col-tiles fast, 250 M-slabs)
// BM=128, BN=64, BK=16; 8 warps (4x2); warp tile 32x32 = 2x4 m16n8k16 tiles
// smem: bf16 pairs with XOR-row swizzle -> conflict-free fragment LDS
__global__ __launch_bounds__(256) void k_gemmB() {
    __shared__ uint32_t Ah[2][128 * 8];
    __shared__ uint32_t Al[2][128 * 8];
    __shared__ uint32_t Bh[2][64 * 8];
    __shared__ uint32_t Bl[2][64 * 8];

    int tid = threadIdx.x;
    int wid = tid >> 5;
    int lane = tid & 31;
    int wm = wid >> 1;            // 0..3
    int wn = wid & 1;             // 0..1
    int lr = lane >> 2;           // 0..7
    int pc = lane & 3;            // 0..3

    int bm = blockIdx.y * 128;
    int col0 = blockIdx.x * 64;

    float acc[2][4][4];
    #pragma unroll
    for (int i = 0; i < 2; i++)
        #pragma unroll
        for (int j = 0; j < 4; j++)
            #pragma unroll
            for (int k = 0; k < 4; k++) acc[i][j][k] = 0.f;

    // G2S mapping
    int a_row = tid >> 1;         // 0..127
    int a_h   = tid & 1;          // which uint4 of the 32B row chunk
    const uint4* pAh = (const uint4*)(g_x_hi + (size_t)(bm + a_row) * IN_DIM) + a_h;
    const uint4* pAl = (const uint4*)(g_x_lo + (size_t)(bm + a_row) * IN_DIM) + a_h;
    int b_row = (tid & 127) >> 1; // 0..63
    int b_h   = tid & 1;
    const __nv_bfloat16* bSrcBase = (tid < 128) ? g_Wb_hi : g_Wb_lo;
    const uint4* pB = (const uint4*)(bSrcBase + (size_t)(col0 + b_row) * IN_DIM) + b_h;

    int aX = a_row & 7;
    int aBase = a_row * 8;
    int bX = b_row & 7;
    int bBase = b_row * 8;

    // prologue: kt=0 -> buf 0  (kt in uint4 units: kt bf16 /8)
    {
        uint4 vh = pAh[0];
        uint4 vl = pAl[0];
        uint4 vb = pB[0];
        Ah[0][aBase + ((4 * a_h + 0) ^ aX)] = vh.x;
        Ah[0][aBase + ((4 * a_h + 1) ^ aX)] = vh.y;
        Ah[0][aBase + ((4 * a_h + 2) ^ aX)] = vh.z;
        Ah[0][aBase + ((4 * a_h + 3) ^ aX)] = vh.w;
        Al[0][aBase + ((4 * a_h + 0) ^ aX)] = vl.x;
        Al[0][aBase + ((4 * a_h + 1) ^ aX)] = vl.y;
        Al[0][aBase + ((4 * a_h + 2) ^ aX)] = vl.z;
        Al[0][aBase + ((4 * a_h + 3) ^ aX)] = vl.w;
        uint32_t* bD = (tid < 128) ? Bh[0] : Bl[0];
        bD[bBase + ((4 * b_h + 0) ^ bX)] = vb.x;
        bD[bBase + ((4 * b_h + 1) ^ bX)] = vb.y;
        bD[bBase + ((4 * b_h + 2) ^ bX)] = vb.z;
        bD[bBase + ((4 * b_h + 3) ^ bX)] = vb.w;
    }
    __syncthreads();

    int buf = 0;
    for (int kt = 0; kt < IN_DIM; kt += 16) {
        int ktn = kt + 16;
        uint4 vh, vl, vb;
        if (ktn < IN_DIM) {
            int o = ktn >> 3;     // uint4 offset
            vh = pAh[o];
            vl = pAl[o];
            vb = pB[o];
        }

        // fragments
        uint32_t afh[2][4], afl[2][4];
        #pragma unroll
        for (int tm = 0; tm < 2; tm++) {
            int ra = wm * 32 + tm * 16 + lr;
            int rb = ra + 8;
            int sa = ra * 8, xa = ra & 7;
            int sb = rb * 8, xb = rb & 7;
            afh[tm][0] = Ah[buf][sa + (pc ^ xa)];
            afh[tm][1] = Ah[buf][sb + (pc ^ xb)];
            afh[tm][2] = Ah[buf][sa + ((pc + 4) ^ xa)];
            afh[tm][3] = Ah[buf][sb + ((pc + 4) ^ xb)];
            afl[tm][0] = Al[buf][sa + (pc ^ xa)];
            afl[tm][1] = Al[buf][sb + (pc ^ xb)];
            afl[tm][2] = Al[buf][sa + ((pc + 4) ^ xa)];
            afl[tm][3] = Al[buf][sb + ((pc + 4) ^ xb)];
        }
        uint32_t bfh[4][2], bfl[4][2];
        #pragma unroll
        for (int tn = 0; tn < 4; tn++) {
            int n = wn * 32 + tn * 8 + lr;
            int sn = n * 8, xn = n & 7;
            bfh[tn][0] = Bh[buf][sn + (pc ^ xn)];
            bfh[tn][1] = Bh[buf][sn + ((pc + 4) ^ xn)];
            bfl[tn][0] = Bl[buf][sn + (pc ^ xn)];
            bfl[tn][1] = Bl[buf][sn + ((pc + 4) ^ xn)];
        }
        // 3-term: Ah*Bh + Ah*Bl + Al*Bh
        #pragma unroll
        for (int tm = 0; tm < 2; tm++)
            #pragma unroll
            for (int tn = 0; tn < 4; tn++) {
                MMA_BF16(acc[tm][tn], afh[tm], bfh[tn]);
                MMA_BF16(acc[tm][tn], afh[tm], bfl[tn]);
                MMA_BF16(acc[tm][tn], afl[tm], bfh[tn]);
            }

        if (ktn < IN_DIM) {
            int nb = buf ^ 1;
            Ah[nb][aBase + ((4 * a_h + 0) ^ aX)] = vh.x;
            Ah[nb][aBase + ((4 * a_h + 1) ^ aX)] = vh.y;
            Ah[nb][aBase + ((4 * a_h + 2) ^ aX)] = vh.z;
            Ah[nb][aBase + ((4 * a_h + 3) ^ aX)] = vh.w;
            Al[nb][aBase + ((4 * a_h + 0) ^ aX)] = vl.x;
            Al[nb][aBase + ((4 * a_h + 1) ^ aX)] = vl.y;
            Al[nb][aBase + ((4 * a_h + 2) ^ aX)] = vl.z;
            Al[nb][aBase + ((4 * a_h + 3) ^ aX)] = vl.w;
            uint32_t* bD = (tid < 128) ? Bh[nb] : Bl[nb];
            bD[bBase + ((4 * b_h + 0) ^ bX)] = vb.x;
            bD[bBase + ((4 * b_h + 1) ^ bX)] = vb.y;
            bD[bBase + ((4 * b_h + 2) ^ bX)] = vb.z;
            bD[bBase + ((4 * b_h + 3) ^ bX)] = vb.w;
            __syncthreads();
            buf = nb;
        }
    }

    // epilogue: C fragments -> g_Y
    #pragma unroll
    for (int tm = 0; tm < 2; tm++) {
        int row_base = bm + wm * 32 + tm * 16 + lr;
        #pragma unroll
        for (int tn = 0; tn < 4; tn++) {
            int col = col0 + wn * 32 + tn * 8 + pc * 2;
            float* d0 = g_Y + (size_t)row_base * 512 + col;
            float* d1 = g_Y + (size_t)(row_base + 8) * 512 + col;
            *(float2*)d0 = make_float2(acc[tm][tn][0], acc[tm][tn][1]);
            *(float2*)d1 = make_float2(acc[tm][tn][2], acc[tm][tn][3]);
        }
    }
}

// ---------------- S16 = x @ [Wla | Wra]  [N,16] ----------------
__global__ __launch_bounds__(256) void k_s16(const float* __restrict__ x,
                                             const float* __restrict__ Wla,
                                             const float* __restrict__ Wra) {
    int node = (blockIdx.x * blockDim.x + threadIdx.x) >> 5;
    int lane = threadIdx.x & 31;
    if (node >= N_NODES) return;
    const float4* Wl4 = (const float4*)Wla;
    const float4* Wr4 = (const float4*)Wra;
    float al[8], ar[8];
    #pragma unroll
    for (int c = 0; c < 8; c++) { al[c] = 0.f; ar[c] = 0.f; }
    const float* xr = x + (size_t)node * IN_DIM;
    for (int k0 = 0; k0 < IN_DIM; k0 += 32) {
        int k = k0 + lane;
        float xx = xr[k];
        float4 l0 = Wl4[k * 2], l1 = Wl4[k * 2 + 1];
        float4 r0 = Wr4[k * 2], r1 = Wr4[k * 2 + 1];
        al[0] += xx * l0.x; al[1] += xx * l0.y; al[2] += xx * l0.z; al[3] += xx * l0.w;
        al[4] += xx * l1.x; al[5] += xx * l1.y; al[6] += xx * l1.z; al[7] += xx * l1.w;
        ar[0] += xx * r0.x; ar[1] += xx * r0.y; ar[2] += xx * r0.z; ar[3] += xx * r0.w;
        ar[4] += xx * r1.x; ar[5] += xx * r1.y; ar[6] += xx * r1.z; ar[7] += xx * r1.w;
    }
    #pragma unroll
    for (int o = 16; o > 0; o >>= 1) {
        #pragma unroll
        for (int c = 0; c < 8; c++) {
            al[c] += __shfl_xor_sync(0xFFFFFFFFu, al[c], o);
            ar[c] += __shfl_xor_sync(0xFFFFFFFFu, ar[c], o);
        }
    }
    if (lane == 0) {
        float4* out = (float4*)(g_S16 + (size_t)node * 16);
        out[0] = make_float4(al[0], al[1], al[2], al[3]);
        out[1] = make_float4(al[4], al[5], al[6], al[7]);
        out[2] = make_float4(ar[0], ar[1], ar[2], ar[3]);
        out[3] = make_float4(ar[4], ar[5], ar[6], ar[7]);
    }
}

// ---------------- fused aggregation + Z + softmax(S) ----------------
__global__ __launch_bounds__(256) void k_agg_fuse(const float* __restrict__ bl1,
                                                  const float* __restrict__ bla) {
    int node = (blockIdx.x * blockDim.x + threadIdx.x) >> 5;
    int lane = threadIdx.x & 31;
    if (node >= N_NODES) return;
    int beg = g_off[node], end = g_off[node + 1];

    float4 a0 = make_float4(0.f, 0.f, 0.f, 0.f);
    float4 a1 = a0;
    float sacc = 0.f;
    for (int p = beg; p < end; p++) {
        int s = g_csr_src[p];
        const float4* row = (const float4*)(g_Y + (size_t)s * 512);
        float4 v0 = row[lane * 2];
        float4 v1 = row[lane * 2 + 1];
        a0.x += v0.x; a0.y += v0.y; a0.z += v0.z; a0.w += v0.w;
        a1.x += v1.x; a1.y += v1.y; a1.z += v1.z; a1.w += v1.w;
        if (lane < 8) sacc += g_S16[(size_t)s * 16 + lane];
    }
    float inv = (end > beg) ? 1.f / (float)(end - beg) : 0.f;

    const float4* yr = (const float4*)(g_Y + (size_t)node * 512 + 256);
    float4 r0 = yr[lane * 2], r1 = yr[lane * 2 + 1];
    const float4* bb4 = (const float4*)bl1;
    float4 b0 = bb4[lane * 2], b1 = bb4[lane * 2 + 1];
    float4 z0, z1;
    z0.x = fmaxf(a0.x * inv + r0.x + b0.x, 0.f);
    z0.y = fmaxf(a0.y * inv + r0.y + b0.y, 0.f);
    z0.z = fmaxf(a0.z * inv + r0.z + b0.z, 0.f);
    z0.w = fmaxf(a0.w * inv + r0.w + b0.w, 0.f);
    z1.x = fmaxf(a1.x * inv + r1.x + b1.x, 0.f);
    z1.y = fmaxf(a1.y * inv + r1.y + b1.y, 0.f);
    z1.z = fmaxf(a1.z * inv + r1.z + b1.z, 0.f);
    z1.w = fmaxf(a1.w * inv + r1.w + b1.w, 0.f);
    float4* zo = (float4*)(g_Z + (size_t)node * HID);
    zo[lane * 2] = z0;
    zo[lane * 2 + 1] = z1;

    float sval = 0.f;
    if (lane < 8)
        sval = sacc * inv + g_S16[(size_t)node * 16 + 8 + lane] + bla[lane];
    float m = sval;
    #pragma unroll
    for (int o = 4; o > 0; o >>= 1)
        m = fmaxf(m, __shfl_xor_sync(0xFFFFFFFFu, m, o, 8));
    float e = expf(sval - m);
    float ssum = e;
    #pragma unroll
    for (int o = 4; o > 0; o >>= 1)
        ssum += __shfl_xor_sync(0xFFFFFFFFu, ssum, o, 8);
    if (lane < 8)
        g_Ss[(size_t)node * 8 + lane] = e / ssum;
}

// ---------------- Xp[g,c,h] = sum_i Ss[i,c] * Z[i,h] ----------------
__global__ __launch_bounds__(256) void k_xp() {
    int g = blockIdx.x;
    int t = threadIdx.x;
    __shared__ __align__(16) float sS[64][8];
    float acc[8];
    #pragma unroll
    for (int c = 0; c < 8; c++) acc[c] = 0.f;
    for (int base = 0; base < NPG; base += 64) {
        int nchunk = min(64, NPG - base);
        for (int idx = t; idx < nchunk * 8; idx += 256)
            sS[idx >> 3][idx & 7] = g_Ss[(size_t)(g * NPG + base) * 8 + idx];
        __syncthreads();
        for (int i = 0; i < nchunk; i++) {
            float z = g_Z[(size_t)(g * NPG + base + i) * HID + t];
            #pragma unroll
            for (int c = 0; c < 8; c++) acc[c] += sS[i][c] * z;
        }
        __syncthreads();
    }
    #pragma unroll
    for (int c = 0; c < 8; c++)
        g_Xp[g * (NC * HID) + c * HID + t] = acc[c];
}

// ---------------- Ap[g,i,j] ----------------
__global__ __launch_bounds__(256) void k_ap() {
    int g = blockIdx.x;
    int tid = threadIdx.x;
    __shared__ __align__(16) float es[256][8];
    __shared__ __align__(16) float ed[256][8];
    __shared__ float apsh[64];
    if (tid < 64) apsh[tid] = 0.f;
    int p0 = g_off[g * NPG];
    int p1 = g_off[(g + 1) * NPG];
    int ij = tid & 63, egrp = tid >> 6;
    int i = ij >> 3, j = ij & 7;
    float acc = 0.f;
    __syncthreads();
    for (int base = p0; base < p1; base += 256) {
        int n = min(256, p1 - base);
        for (int idx = tid; idx < n; idx += 256) {
            int s = g_csr_src[base + idx];
            int d = g_csr_dst[base + idx];
            const float4* Ps = (const float4*)(g_Ss + (size_t)s * 8);
            const float4* Pd = (const float4*)(g_Ss + (size_t)d * 8);
            ((float4*)es[idx])[0] = Ps[0];
            ((float4*)es[idx])[1] = Ps[1];
            ((float4*)ed[idx])[0] = Pd[0];
            ((float4*)ed[idx])[1] = Pd[1];
        }
        __syncthreads();
        for (int e = egrp; e < n; e += 4)
            acc += es[e][i] * ed[e][j];
        __syncthreads();
    }
    atomicAdd(&apsh[ij], acc);
    __syncthreads();
    if (tid < 64) g_Ap[g * 64 + tid] = apsh[tid];
}

// ---------------- pooled SAGE ----------------
__global__ __launch_bounds__(256) void k_pool(const float* __restrict__ Wl2,
                                              const float* __restrict__ bl2,
                                              const float* __restrict__ Wr2) {
    int g = blockIdx.x;
    int t = threadIdx.x;
    __shared__ float sXp[8][HID];
    __shared__ float sA2[8][HID];
    __shared__ float smask[8][8];
    __shared__ float sdeg[8];
    #pragma unroll
    for (int c = 0; c < 8; c++) sXp[c][t] = g_Xp[g * (NC * HID) + c * HID + t];
    if (t < 64) smask[t >> 3][t & 7] = (g_Ap[g * 64 + t] != 0.f) ? 1.f : 0.f;
    __syncthreads();
    if (t < 8) {
        float d = 0.f;
        #pragma unroll
        for (int ii = 0; ii < 8; ii++) d += smask[ii][t];
        sdeg[t] = d;
    }
    __syncthreads();
    #pragma unroll
    for (int j = 0; j < 8; j++) {
        float a = 0.f;
        #pragma unroll
        for (int ii = 0; ii < 8; ii++) a += smask[ii][j] * sXp[ii][t];
        float d = sdeg[j];
        sA2[j][t] = (d > 0.f) ? a / d : 0.f;
    }
    __syncthreads();
    float bb = bl2[t];
    #pragma unroll
    for (int j = 0; j < 8; j++) {
        float a = bb;
        for (int k = 0; k < HID; k++)
            a += sA2[j][k] * Wl2[k * HID + t] + sXp[j][k] * Wr2[k * HID + t];
        g_Zp[g * (NC * HID) + j * HID + t] = a > 0.f ? a : 0.f;
    }
}

// ---------------- classifier ----------------
__global__ __launch_bounds__(256) void k_cls(const float* __restrict__ Wc1,
                                             const float* __restrict__ bc1,
                                             const float* __restrict__ Wc2,
                                             const float* __restrict__ bc2,
                                             float* __restrict__ out) {
    int g = blockIdx.x;
    int t = threadIdx.x;
    __shared__ float sZ[NC * HID];
    __shared__ float sh[256];
    #pragma unroll
    for (int u = 0; u < 8; u++) sZ[u * 256 + t] = g_Zp[g * (NC * HID) + u * 256 + t];
    __syncthreads();
    float a = bc1[t];
    for (int k = 0; k < NC * HID; k++)
        a += sZ[k] * Wc1[(size_t)k * HID + t];
    float h = a > 0.f ? a : 0.f;
    sh[t] = h * Wc2[t];
    __syncthreads();
    #pragma unroll
    for (int s = 128; s > 0; s >>= 1) {
        if (t < s) sh[t] += sh[t + s];
        __syncthreads();
    }
    if (t == 0) out[g] = sh[0] + bc2[0];
}

// ---------------- launch ----------------
extern "C" void kernel_launch(void* const* d_in, const int* in_sizes, int n_in,
                              void* d_out, int out_size) {
    const float* x   = (const float*)d_in[0];
    const int*   ei  = (const int*)d_in[1];
    const float* Wl1 = (const float*)d_in[3];
    const float* bl1 = (const float*)d_in[4];
    const float* Wr1 = (const float*)d_in[5];
    const float* Wla = (const float*)d_in[6];
    const float* bla = (const float*)d_in[7];
    const float* Wra = (const float*)d_in[8];
    const float* Wl2 = (const float*)d_in[9];
    const float* bl2 = (const float*)d_in[10];
    const float* Wr2 = (const float*)d_in[11];
    const float* Wc1 = (const float*)d_in[12];
    const float* bc1 = (const float*)d_in[13];
    const float* Wc2 = (const float*)d_in[14];
    const float* bc2 = (const float*)d_in[15];
    float* out = (float*)d_out;

    const int* src = ei;
    const int* dst = ei + N_EDGES;

    // gemm at launch index 3 (observed ncu capture slot)
    k_zero_cnt<<<(N_NODES + 255) / 256, 256>>>();                     // 0
    k_convW<<<dim3(4, 512), 256>>>(Wl1, Wr1);                         // 1
    k_convX<<<N_NODES * IN_DIM / 4096, 256>>>(x);                     // 2
    k_gemmB<<<dim3(8, N_NODES / 128), 256>>>();                       // 3
    k_hist<<<(N_EDGES + 255) / 256, 256>>>(dst);                      // 4
    k_scan<<<1, 1024>>>();                                            // 5
    k_scatter<<<(N_EDGES + 255) / 256, 256>>>(src, dst);              // 6
    k_s16<<<(N_NODES * 32 + 255) / 256, 256>>>(x, Wla, Wra);          // 7
    k_agg_fuse<<<(N_NODES * 32 + 255) / 256, 256>>>(bl1, bla);        // 8
    k_xp<<<NUM_G, 256>>>();
    k_ap<<<NUM_G, 256>>>();
    k_pool<<<NUM_G, 256>>>(Wl2, bl2, Wr2);
    k_cls<<<NUM_G, 256>>>(Wc1, bc1, Wc2, bc2, out);
}